// round 1
// baseline (speedup 1.0000x reference)
#include <cuda_runtime.h>

#define Bx   4
#define Sx   1024
#define Hx   8
#define Dx   64
#define HDx  512
#define EMBx 512
#define XLx  1024
#define Jx   2048      // XL + S
#define KKx  32

// ---------------- device scratch (no allocations allowed) ----------------
__device__ float g_q[Bx * Hx * Sx * Dx];        // [b,h,s,d]
__device__ float g_k[Bx * Hx * Jx * Dx];        // [b,h,j,d]  (xl ++ current)
__device__ float g_v[Bx * Hx * Jx * Dx];        // [b,h,j,d]
__device__ float g_loc[Bx * Hx * Sx * Dx];      // g * local attn out
__device__ float g_merged[Bx * Sx * HDx];       // [b*s, h*d]  GEMM-ready

// ---------------------------------------------------------------------------
// xl_memory [b, j, 2, HD] -> g_k / g_v rows 0..XL-1 in [b,h,j,d] layout
// ---------------------------------------------------------------------------
__global__ __launch_bounds__(256) void xl_copy(const float* __restrict__ xlm)
{
    int idx = blockIdx.x * blockDim.x + threadIdx.x;  // over float4s
    const int total = Bx * XLx * 2 * (HDx / 4);       // 1,048,576
    if (idx >= total) return;
    int n4 = idx & 127;        // HD/4 = 128
    int rest = idx >> 7;
    int c = rest & 1;  rest >>= 1;
    int j = rest & 1023;
    int b = rest >> 10;
    float4 f = ((const float4*)xlm)[idx];
    int n = n4 * 4;
    int h = n >> 6, d = n & 63;
    float* dst = (c ? g_v : g_k) + (((size_t)(b * Hx + h)) * Jx + j) * Dx + d;
    *(float4*)dst = f;
}

// ---------------------------------------------------------------------------
// C[M=4096, N=512] = A[M,512] @ W[N=512,512]^T + bias, fused epilogues:
//   mode 0: write g_q  [b,h,s,d]
//   mode 1: write g_k  rows XL.. and kv-out slot 0
//   mode 2: write g_v  rows XL.. and kv-out slot 1
//   mode 3: A := g_merged, write plain row-major to dst1 (final out)
// ---------------------------------------------------------------------------
__global__ __launch_bounds__(256) void gemm512(const float* __restrict__ A,
                                               const float* __restrict__ W,
                                               const float* __restrict__ bias,
                                               float* __restrict__ dst1,
                                               int mode)
{
    __shared__ float As[16][68];
    __shared__ float Ws[16][68];

    const float* Ap0 = (mode == 3) ? g_merged : A;

    int tid = threadIdx.x;
    int tx = tid & 15, ty = tid >> 4;
    int m0 = blockIdx.x * 64, n0 = blockIdx.y * 64;

    int lr = tid >> 2;            // row within 64-tile
    int lc = (tid & 3) << 2;      // k offset 0,4,8,12

    const float* Ap = Ap0 + (size_t)(m0 + lr) * 512 + lc;
    const float* Wp = W   + (size_t)(n0 + lr) * 512 + lc;

    float acc[4][4];
#pragma unroll
    for (int i = 0; i < 4; i++)
#pragma unroll
        for (int j = 0; j < 4; j++) acc[i][j] = 0.f;

    for (int k0 = 0; k0 < 512; k0 += 16) {
        float4 av = *(const float4*)(Ap + k0);
        float4 wv = *(const float4*)(Wp + k0);
        __syncthreads();
        As[lc + 0][lr] = av.x; As[lc + 1][lr] = av.y;
        As[lc + 2][lr] = av.z; As[lc + 3][lr] = av.w;
        Ws[lc + 0][lr] = wv.x; Ws[lc + 1][lr] = wv.y;
        Ws[lc + 2][lr] = wv.z; Ws[lc + 3][lr] = wv.w;
        __syncthreads();
#pragma unroll
        for (int kk = 0; kk < 16; kk++) {
            float4 af = *(const float4*)&As[kk][ty * 4];
            float4 wf = *(const float4*)&Ws[kk][tx * 4];
            float aa[4] = {af.x, af.y, af.z, af.w};
            float ww[4] = {wf.x, wf.y, wf.z, wf.w};
#pragma unroll
            for (int i = 0; i < 4; i++)
#pragma unroll
                for (int j = 0; j < 4; j++)
                    acc[i][j] = fmaf(aa[i], ww[j], acc[i][j]);
        }
    }

#pragma unroll
    for (int i = 0; i < 4; i++) {
        int m = m0 + ty * 4 + i;
        int b = m >> 10, s = m & 1023;
#pragma unroll
        for (int j = 0; j < 4; j++) {
            int n = n0 + tx * 4 + j;
            float c = acc[i][j] + bias[n];
            int h = n >> 6, d = n & 63;
            if (mode == 0) {
                g_q[(((size_t)(b * Hx + h)) * Sx + s) * Dx + d] = c;
            } else if (mode == 1) {
                g_k[(((size_t)(b * Hx + h)) * Jx + XLx + s) * Dx + d] = c;
                dst1[(((size_t)(b * Sx + s)) * 2 + 0) * HDx + n] = c;
            } else if (mode == 2) {
                g_v[(((size_t)(b * Hx + h)) * Jx + XLx + s) * Dx + d] = c;
                dst1[(((size_t)(b * Sx + s)) * 2 + 1) * HDx + n] = c;
            } else {
                dst1[(size_t)m * EMBx + n] = c;
            }
        }
    }
}

// ---------------------------------------------------------------------------
// Local causal XL attention, flash-style. One block = (b,h) x 64-query tile.
// scores = (q.k + rel_pos) * scale, mask kj > qi + XL, online softmax, P.V.
// Writes g * O / l  into g_loc.
// ---------------------------------------------------------------------------
__global__ __launch_bounds__(256) void local_attn(const float* __restrict__ rel,
                                                  const float* __restrict__ gate)
{
    extern __shared__ float sm[];
    float* Qs = sm;              // [64][68] d-major:  Qs[d*68 + q]
    float* Ks = sm + 64 * 68;    // [64][68] d-major:  Ks[d*68 + k]
    float* Vs = sm + 2 * 64 * 68;// [64][68] key-major: Vs[k*68 + d]
    float* Ps = sm + 3 * 64 * 68;// [64][68] key-major: Ps[k*68 + q]

    int bh = blockIdx.x;               // 0..31, b = bh/8, h = bh%8
    int h = bh & 7;
    int qt = blockIdx.y;               // 0..15
    int i0 = qt * 64;
    int tid = threadIdx.x;
    int tx = tid & 15, ty = tid >> 4;

    // load Q tile (d-major)
    const float* qbase = g_q + (((size_t)bh) * Sx + i0) * Dx;
    for (int idx = tid; idx < 1024; idx += 256) {
        int row = idx >> 4, c4 = idx & 15;
        float4 f = *(const float4*)(qbase + row * 64 + c4 * 4);
        Qs[(c4 * 4 + 0) * 68 + row] = f.x;
        Qs[(c4 * 4 + 1) * 68 + row] = f.y;
        Qs[(c4 * 4 + 2) * 68 + row] = f.z;
        Qs[(c4 * 4 + 3) * 68 + row] = f.w;
    }

    float o[4][4];
    float m[4], l[4];
#pragma unroll
    for (int i = 0; i < 4; i++) {
        m[i] = -1e30f; l[i] = 0.f;
#pragma unroll
        for (int j = 0; j < 4; j++) o[i][j] = 0.f;
    }

    int ntiles = qt + 17;  // keys up to i0 + 63 + XL inclusive
    const float* kbase = g_k + ((size_t)bh) * Jx * Dx;
    const float* vbase = g_v + ((size_t)bh) * Jx * Dx;
    const float* relh  = rel + (size_t)h * Sx * Jx;

    for (int t = 0; t < ntiles; t++) {
        int j0 = t * 64;
        __syncthreads();   // previous P.V done before overwriting tiles
        for (int idx = tid; idx < 1024; idx += 256) {
            int row = idx >> 4, c4 = idx & 15;
            float4 f = *(const float4*)(kbase + (size_t)(j0 + row) * 64 + c4 * 4);
            Ks[(c4 * 4 + 0) * 68 + row] = f.x;
            Ks[(c4 * 4 + 1) * 68 + row] = f.y;
            Ks[(c4 * 4 + 2) * 68 + row] = f.z;
            Ks[(c4 * 4 + 3) * 68 + row] = f.w;
            float4 g4 = *(const float4*)(vbase + (size_t)(j0 + row) * 64 + c4 * 4);
            *(float4*)&Vs[row * 68 + c4 * 4] = g4;
        }
        __syncthreads();

        // S = Q K^T  (64x64, per-thread 4x4)
        float s[4][4];
#pragma unroll
        for (int i = 0; i < 4; i++)
#pragma unroll
            for (int j = 0; j < 4; j++) s[i][j] = 0.f;
#pragma unroll 8
        for (int d = 0; d < 64; d++) {
            float4 qf = *(const float4*)&Qs[d * 68 + ty * 4];
            float4 kf = *(const float4*)&Ks[d * 68 + tx * 4];
            float qa[4] = {qf.x, qf.y, qf.z, qf.w};
            float ka[4] = {kf.x, kf.y, kf.z, kf.w};
#pragma unroll
            for (int i = 0; i < 4; i++)
#pragma unroll
                for (int j = 0; j < 4; j++)
                    s[i][j] = fmaf(qa[i], ka[j], s[i][j]);
        }

        // rel_pos add, scale, causal mask
#pragma unroll
        for (int i = 0; i < 4; i++) {
            int qi = i0 + ty * 4 + i;
            const float* rrow = relh + (size_t)qi * Jx + j0 + tx * 4;
#pragma unroll
            for (int j = 0; j < 4; j++) {
                int kj = j0 + tx * 4 + j;
                s[i][j] = (kj <= qi + XLx) ? (s[i][j] + rrow[j]) * 0.125f
                                           : -1e30f;
            }
        }

        // online softmax (reduce over the 16 tx lanes of each row)
#pragma unroll
        for (int i = 0; i < 4; i++) {
            float rm = fmaxf(fmaxf(s[i][0], s[i][1]), fmaxf(s[i][2], s[i][3]));
            rm = fmaxf(rm, __shfl_xor_sync(0xffffffffu, rm, 8));
            rm = fmaxf(rm, __shfl_xor_sync(0xffffffffu, rm, 4));
            rm = fmaxf(rm, __shfl_xor_sync(0xffffffffu, rm, 2));
            rm = fmaxf(rm, __shfl_xor_sync(0xffffffffu, rm, 1));
            float mn = fmaxf(m[i], rm);
            float alpha = __expf(m[i] - mn);
            float rs = 0.f;
#pragma unroll
            for (int j = 0; j < 4; j++) {
                float p = __expf(s[i][j] - mn);
                rs += p;
                Ps[(tx * 4 + j) * 68 + (ty * 4 + i)] = p;
            }
            rs += __shfl_xor_sync(0xffffffffu, rs, 8);
            rs += __shfl_xor_sync(0xffffffffu, rs, 4);
            rs += __shfl_xor_sync(0xffffffffu, rs, 2);
            rs += __shfl_xor_sync(0xffffffffu, rs, 1);
            l[i] = l[i] * alpha + rs;
            m[i] = mn;
#pragma unroll
            for (int j = 0; j < 4; j++) o[i][j] *= alpha;
        }
        __syncthreads();   // Ps visible to everyone

        // O += P V  (per-thread 4 queries x 4 dims)
#pragma unroll 8
        for (int ky = 0; ky < 64; ky++) {
            float4 pf = *(const float4*)&Ps[ky * 68 + ty * 4];
            float4 vf = *(const float4*)&Vs[ky * 68 + tx * 4];
            float pa[4] = {pf.x, pf.y, pf.z, pf.w};
            float va[4] = {vf.x, vf.y, vf.z, vf.w};
#pragma unroll
            for (int i = 0; i < 4; i++)
#pragma unroll
                for (int j = 0; j < 4; j++)
                    o[i][j] = fmaf(pa[i], va[j], o[i][j]);
        }
    }

    float gsig = 1.f / (1.f + __expf(-gate[h]));
#pragma unroll
    for (int i = 0; i < 4; i++) {
        float inv = gsig / l[i];
        size_t base = (((size_t)bh) * Sx + i0 + ty * 4 + i) * Dx + tx * 4;
        float4 st;
        st.x = o[i][0] * inv; st.y = o[i][1] * inv;
        st.z = o[i][2] * inv; st.w = o[i][3] * inv;
        *(float4*)&g_loc[base] = st;
    }
}

// ---------------------------------------------------------------------------
// kNN external-memory attention + gated merge.
// One warp = one (b, h, s): lane = retrieved key index (KK = 32).
// merged[b,s,h*64+d] = g_loc (already g-scaled) + (1-g) * softmax(qk)*v
// ---------------------------------------------------------------------------
__global__ __launch_bounds__(64) void knn_kernel(const float* __restrict__ knn,
                                                 const float* __restrict__ gate,
                                                 float* __restrict__ unused)
{
    __shared__ float qsh[2][64];
    __shared__ float vsh[2][32][68];

    int s = blockIdx.x, b = blockIdx.y, hp = blockIdx.z;
    int wid = threadIdx.x >> 5, lane = threadIdx.x & 31;
    int h = hp * 2 + wid;

    const float* qp = g_q + (((size_t)(b * Hx + h)) * Sx + s) * Dx;
    qsh[wid][lane]      = qp[lane];
    qsh[wid][lane + 32] = qp[lane + 32];
    __syncwarp();

    const float* kp = knn + ((((size_t)(b * Sx + s)) * KKx + lane) * 2 + 0) * HDx
                          + h * 64;
    float sc = 0.f;
#pragma unroll
    for (int i = 0; i < 16; i++) {
        float4 kf = *(const float4*)(kp + i * 4);
        float4 qf = *(const float4*)&qsh[wid][i * 4];
        sc = fmaf(qf.x, kf.x, sc);
        sc = fmaf(qf.y, kf.y, sc);
        sc = fmaf(qf.z, kf.z, sc);
        sc = fmaf(qf.w, kf.w, sc);
    }
    sc *= 0.125f;

    float mx = sc;
    mx = fmaxf(mx, __shfl_xor_sync(0xffffffffu, mx, 16));
    mx = fmaxf(mx, __shfl_xor_sync(0xffffffffu, mx, 8));
    mx = fmaxf(mx, __shfl_xor_sync(0xffffffffu, mx, 4));
    mx = fmaxf(mx, __shfl_xor_sync(0xffffffffu, mx, 2));
    mx = fmaxf(mx, __shfl_xor_sync(0xffffffffu, mx, 1));
    float p = __expf(sc - mx);
    float sum = p;
    sum += __shfl_xor_sync(0xffffffffu, sum, 16);
    sum += __shfl_xor_sync(0xffffffffu, sum, 8);
    sum += __shfl_xor_sync(0xffffffffu, sum, 4);
    sum += __shfl_xor_sync(0xffffffffu, sum, 2);
    sum += __shfl_xor_sync(0xffffffffu, sum, 1);
    p /= sum;

    const float* vp = kp + HDx;  // slot 1 (values)
#pragma unroll
    for (int i = 0; i < 16; i++) {
        float4 vf = *(const float4*)(vp + i * 4);
        vsh[wid][lane][i * 4 + 0] = p * vf.x;
        vsh[wid][lane][i * 4 + 1] = p * vf.y;
        vsh[wid][lane][i * 4 + 2] = p * vf.z;
        vsh[wid][lane][i * 4 + 3] = p * vf.w;
    }
    __syncwarp();

    float acc0 = 0.f, acc1 = 0.f;
#pragma unroll
    for (int kk = 0; kk < 32; kk++) {
        acc0 += vsh[wid][kk][lane];
        acc1 += vsh[wid][kk][lane + 32];
    }

    float g = 1.f / (1.f + __expf(-gate[h]));
    float w = 1.f - g;
    size_t li = (((size_t)(b * Hx + h)) * Sx + s) * Dx;
    size_t mi = ((size_t)(b * Sx + s)) * HDx + h * 64;
    g_merged[mi + lane]      = g_loc[li + lane]      + w * acc0;
    g_merged[mi + lane + 32] = g_loc[li + lane + 32] + w * acc1;
}

// ---------------------------------------------------------------------------
extern "C" void kernel_launch(void* const* d_in, const int* in_sizes, int n_in,
                              void* d_out, int out_size)
{
    (void)in_sizes; (void)n_in; (void)out_size;
    const float* x    = (const float*)d_in[0];
    const float* rel  = (const float*)d_in[1];
    const float* xlm  = (const float*)d_in[2];
    const float* knn  = (const float*)d_in[3];
    const float* Wq   = (const float*)d_in[4];
    const float* bq   = (const float*)d_in[5];
    const float* Wk   = (const float*)d_in[6];
    const float* bk   = (const float*)d_in[7];
    const float* Wv   = (const float*)d_in[8];
    const float* bv   = (const float*)d_in[9];
    const float* Wo   = (const float*)d_in[10];
    const float* bo   = (const float*)d_in[11];
    const float* gate = (const float*)d_in[12];

    float* out   = (float*)d_out;                       // [4,1024,512]
    float* kvout = out + (size_t)Bx * Sx * EMBx;        // [4,1024,2,512]

    xl_copy<<<4096, 256>>>(xlm);

    dim3 gg(64, 8);
    gemm512<<<gg, 256>>>(x, Wq, bq, nullptr, 0);
    gemm512<<<gg, 256>>>(x, Wk, bk, kvout, 1);
    gemm512<<<gg, 256>>>(x, Wv, bv, kvout, 2);

    int smem = 4 * 64 * 68 * (int)sizeof(float);        // 69,632 B
    cudaFuncSetAttribute(local_attn,
                         cudaFuncAttributeMaxDynamicSharedMemorySize, smem);
    local_attn<<<dim3(32, 16), 256, smem>>>(rel, gate);

    knn_kernel<<<dim3(Sx, Bx, Hx / 2), 64>>>(knn, gate, nullptr);

    gemm512<<<gg, 256>>>(nullptr, Wo, bo, out, 3);
}

// round 2
// speedup vs baseline: 1.5161x; 1.5161x over previous
#include <cuda_runtime.h>
#include <cstdint>

#define Bx   4
#define Sx   1024
#define Hx   8
#define Dx   64
#define HDx  512
#define EMBx 512
#define XLx  1024
#define Jx   2048      // XL + S
#define KKx  32

// ---------------- device scratch (no allocations allowed) ----------------
__device__ float g_q[Bx * Hx * Sx * Dx];        // [b,h,s,d]
__device__ float g_k[Bx * Hx * Jx * Dx];        // [b,h,j,d]  (xl ++ current)
__device__ float g_v[Bx * Hx * Jx * Dx];        // [b,h,j,d]
__device__ float g_loc[Bx * Hx * Sx * Dx];      // g * local attn out
__device__ float g_merged[Bx * Sx * HDx];       // [b*s, h*d]  GEMM-ready

// ---------------- tf32 helpers ----------------
__device__ __forceinline__ float tf32r(float x) {
    uint32_t u;
    asm("cvt.rna.tf32.f32 %0, %1;" : "=r"(u) : "f"(x));
    return __uint_as_float(u);
}

__device__ __forceinline__ void mma_tf32(float* c, const float* a, const float* b)
{
    asm volatile(
        "mma.sync.aligned.m16n8k8.row.col.f32.tf32.tf32.f32 "
        "{%0,%1,%2,%3},{%4,%5,%6,%7},{%8,%9},{%0,%1,%2,%3};\n"
        : "+f"(c[0]), "+f"(c[1]), "+f"(c[2]), "+f"(c[3])
        : "r"(__float_as_uint(a[0])), "r"(__float_as_uint(a[1])),
          "r"(__float_as_uint(a[2])), "r"(__float_as_uint(a[3])),
          "r"(__float_as_uint(b[0])), "r"(__float_as_uint(b[1])));
}

// ---------------------------------------------------------------------------
// xl_memory [b, j, 2, HD] -> g_k / g_v rows 0..XL-1 in [b,h,j,d] layout
// ---------------------------------------------------------------------------
__global__ __launch_bounds__(256) void xl_copy(const float* __restrict__ xlm)
{
    int idx = blockIdx.x * blockDim.x + threadIdx.x;  // over float4s
    const int total = Bx * XLx * 2 * (HDx / 4);       // 1,048,576
    if (idx >= total) return;
    int n4 = idx & 127;        // HD/4 = 128
    int rest = idx >> 7;
    int c = rest & 1;  rest >>= 1;
    int j = rest & 1023;
    int b = rest >> 10;
    float4 f = ((const float4*)xlm)[idx];
    int n = n4 * 4;
    int h = n >> 6, d = n & 63;
    float* dst = (c ? g_v : g_k) + (((size_t)(b * Hx + h)) * Jx + j) * Dx + d;
    *(float4*)dst = f;
}

// ---------------------------------------------------------------------------
// tf32 tensor-core GEMM: C[4096,512] = A[4096,512] @ W[512,512]^T + bias
// SPLIT=1 : plain tf32 (used for Q)
// SPLIT=3 : 3xTF32 big/small decomposition (~fp32 accuracy)
// Fused epilogues by mode (same semantics as round 1).
// Block tile 128x64, 256 threads = 8 warps (4 along M x 2 along N),
// warp tile 32x32 = 2 m16 x 4 n8 mma tiles, k-chunks of 32.
// ---------------------------------------------------------------------------
template<int SPLIT>
__global__ __launch_bounds__(256) void gemm_mma(const float* __restrict__ A,
                                                const float* __restrict__ W,
                                                const float* __restrict__ bias,
                                                float* __restrict__ dst1,
                                                int mode)
{
    extern __shared__ float smg[];
    float* Ab = smg;                     // [128][36]
    float* Bb = Ab + 128 * 36;           // [64][36]
    float* Al = Bb + 64 * 36;            // SPLIT==3 only
    float* Bl = Al + 128 * 36;

    const float* Ap0 = (mode == 3) ? g_merged : A;

    int tid = threadIdx.x;
    int wid = tid >> 5, lane = tid & 31;
    int wm = wid & 3, wn = wid >> 1 >> 1 >> 0;  // placeholder (fixed below)
    wn = wid >> 2;
    int g = lane >> 2, tig = lane & 3;
    int m0 = blockIdx.x * 128, n0 = blockIdx.y * 64;

    float acc[2][4][4];
#pragma unroll
    for (int i = 0; i < 2; i++)
#pragma unroll
        for (int j = 0; j < 4; j++)
#pragma unroll
            for (int e = 0; e < 4; e++) acc[i][j][e] = 0.f;

    // global load assignments
    int a_row = tid >> 1;                 // 0..127
    int a_c0  = (tid & 1) * 16;           // float offset in 32-k chunk
    int b_row = tid >> 2;                 // 0..63
    int b_c0  = (tid & 3) * 8;

    const float* Agp = Ap0 + (size_t)(m0 + a_row) * 512 + a_c0;
    const float* Wgp = W   + (size_t)(n0 + b_row) * 512 + b_c0;

    for (int kc = 0; kc < 16; kc++) {
        int k0 = kc * 32;
        __syncthreads();
        // A tile: 16 floats/thread
#pragma unroll
        for (int i = 0; i < 4; i++) {
            float4 f = *(const float4*)(Agp + k0 + i * 4);
            float4 bg, sl;
            bg.x = tf32r(f.x); bg.y = tf32r(f.y);
            bg.z = tf32r(f.z); bg.w = tf32r(f.w);
            *(float4*)&Ab[a_row * 36 + a_c0 + i * 4] = bg;
            if (SPLIT == 3) {
                sl.x = tf32r(f.x - bg.x); sl.y = tf32r(f.y - bg.y);
                sl.z = tf32r(f.z - bg.z); sl.w = tf32r(f.w - bg.w);
                *(float4*)&Al[a_row * 36 + a_c0 + i * 4] = sl;
            }
        }
        // B tile: 8 floats/thread
#pragma unroll
        for (int i = 0; i < 2; i++) {
            float4 f = *(const float4*)(Wgp + k0 + i * 4);
            float4 bg, sl;
            bg.x = tf32r(f.x); bg.y = tf32r(f.y);
            bg.z = tf32r(f.z); bg.w = tf32r(f.w);
            *(float4*)&Bb[b_row * 36 + b_c0 + i * 4] = bg;
            if (SPLIT == 3) {
                sl.x = tf32r(f.x - bg.x); sl.y = tf32r(f.y - bg.y);
                sl.z = tf32r(f.z - bg.z); sl.w = tf32r(f.w - bg.w);
                *(float4*)&Bl[b_row * 36 + b_c0 + i * 4] = sl;
            }
        }
        __syncthreads();

#pragma unroll
        for (int kk = 0; kk < 4; kk++) {
            int kb = kk * 8;
            float a[2][4], as[2][4];
#pragma unroll
            for (int mi = 0; mi < 2; mi++) {
                int base = wm * 32 + mi * 16;
                a[mi][0] = Ab[(base + g)     * 36 + kb + tig];
                a[mi][1] = Ab[(base + g + 8) * 36 + kb + tig];
                a[mi][2] = Ab[(base + g)     * 36 + kb + tig + 4];
                a[mi][3] = Ab[(base + g + 8) * 36 + kb + tig + 4];
                if (SPLIT == 3) {
                    as[mi][0] = Al[(base + g)     * 36 + kb + tig];
                    as[mi][1] = Al[(base + g + 8) * 36 + kb + tig];
                    as[mi][2] = Al[(base + g)     * 36 + kb + tig + 4];
                    as[mi][3] = Al[(base + g + 8) * 36 + kb + tig + 4];
                }
            }
            float b[4][2], bs[4][2];
#pragma unroll
            for (int ni = 0; ni < 4; ni++) {
                int nb = wn * 32 + ni * 8;
                b[ni][0] = Bb[(nb + g) * 36 + kb + tig];
                b[ni][1] = Bb[(nb + g) * 36 + kb + tig + 4];
                if (SPLIT == 3) {
                    bs[ni][0] = Bl[(nb + g) * 36 + kb + tig];
                    bs[ni][1] = Bl[(nb + g) * 36 + kb + tig + 4];
                }
            }
#pragma unroll
            for (int mi = 0; mi < 2; mi++)
#pragma unroll
                for (int ni = 0; ni < 4; ni++) {
                    mma_tf32(acc[mi][ni], a[mi], b[ni]);
                    if (SPLIT == 3) {
                        mma_tf32(acc[mi][ni], a[mi], bs[ni]);
                        mma_tf32(acc[mi][ni], as[mi], b[ni]);
                    }
                }
        }
    }

    // epilogue
#pragma unroll
    for (int mi = 0; mi < 2; mi++) {
#pragma unroll
        for (int ni = 0; ni < 4; ni++) {
#pragma unroll
            for (int e = 0; e < 4; e++) {
                int m = m0 + wm * 32 + mi * 16 + g + ((e >> 1) * 8);
                int n = n0 + wn * 32 + ni * 8 + tig * 2 + (e & 1);
                float c = acc[mi][ni][e] + bias[n];
                int b = m >> 10, s = m & 1023;
                int h = n >> 6, d = n & 63;
                if (mode == 0) {
                    g_q[(((size_t)(b * Hx + h)) * Sx + s) * Dx + d] = c;
                } else if (mode == 1) {
                    g_k[(((size_t)(b * Hx + h)) * Jx + XLx + s) * Dx + d] = c;
                    dst1[(((size_t)(b * Sx + s)) * 2 + 0) * HDx + n] = c;
                } else if (mode == 2) {
                    g_v[(((size_t)(b * Hx + h)) * Jx + XLx + s) * Dx + d] = c;
                    dst1[(((size_t)(b * Sx + s)) * 2 + 1) * HDx + n] = c;
                } else {
                    dst1[(size_t)m * EMBx + n] = c;
                }
            }
        }
    }
}

// ---------------------------------------------------------------------------
// Local causal XL attention with tf32 tensor cores.
// Block = (b,h) x 64-query tile, 256 thr = 8 warps:
// warp_m = wid&3 (16-query strip), warp_n = wid>>2 (32-key / 32-dim half).
// ---------------------------------------------------------------------------
__global__ __launch_bounds__(256) void local_attn_mma(const float* __restrict__ rel,
                                                      const float* __restrict__ gate)
{
    extern __shared__ float sm[];
    float* Qs = sm;                  // [d][72] over q   (tf32-rounded)
    float* Ks = Qs + 64 * 72;        // [d][72] over key
    float* Vs = Ks + 64 * 72;        // [key][72] over d
    float* Ps = Vs + 64 * 72;        // [key][72] over q
    float* Mh = Ps + 64 * 72;        // [2][64] row-max halves
    float* Lh = Mh + 128;            // [2][64] row-sum halves

    int bh = blockIdx.x;             // b*8 + h
    int h = bh & 7;
    int qt = blockIdx.y;
    int i0 = qt * 64;
    int tid = threadIdx.x;
    int wid = tid >> 5, lane = tid & 31;
    int wm = wid & 3, wn = wid >> 2;
    int g = lane >> 2, tig = lane & 3;
    int r0 = wm * 16 + g, r1 = r0 + 8;

    // load Q tile -> d-major, tf32 rounded
    const float* qbase = g_q + (((size_t)bh) * Sx + i0) * Dx;
    for (int idx = tid; idx < 1024; idx += 256) {
        int row = idx >> 4, c4 = idx & 15;
        float4 f = *(const float4*)(qbase + row * 64 + c4 * 4);
        Qs[(c4 * 4 + 0) * 72 + row] = tf32r(f.x);
        Qs[(c4 * 4 + 1) * 72 + row] = tf32r(f.y);
        Qs[(c4 * 4 + 2) * 72 + row] = tf32r(f.z);
        Qs[(c4 * 4 + 3) * 72 + row] = tf32r(f.w);
    }

    float o[4][4];
#pragma unroll
    for (int i = 0; i < 4; i++)
#pragma unroll
        for (int j = 0; j < 4; j++) o[i][j] = 0.f;
    float mrow0 = -1e30f, mrow1 = -1e30f, lrow0 = 0.f, lrow1 = 0.f;

    int ntiles = qt + 17;
    const float* kbase = g_k + ((size_t)bh) * Jx * Dx;
    const float* vbase = g_v + ((size_t)bh) * Jx * Dx;
    const float* relh  = rel + (size_t)h * Sx * Jx;
    const int qi0 = i0 + r0, qi1 = i0 + r1;
    const float* relrow0 = relh + (size_t)qi0 * Jx;
    const float* relrow1 = relh + (size_t)qi1 * Jx;

    for (int t = 0; t < ntiles; t++) {
        int j0 = t * 64;
        __syncthreads();   // prior S/PV reads of Ks/Vs done
        for (int idx = tid; idx < 1024; idx += 256) {
            int row = idx >> 4, c4 = idx & 15;
            float4 f = *(const float4*)(kbase + (size_t)(j0 + row) * 64 + c4 * 4);
            Ks[(c4 * 4 + 0) * 72 + row] = tf32r(f.x);
            Ks[(c4 * 4 + 1) * 72 + row] = tf32r(f.y);
            Ks[(c4 * 4 + 2) * 72 + row] = tf32r(f.z);
            Ks[(c4 * 4 + 3) * 72 + row] = tf32r(f.w);
            float4 v = *(const float4*)(vbase + (size_t)(j0 + row) * 64 + c4 * 4);
            float4 vr;
            vr.x = tf32r(v.x); vr.y = tf32r(v.y);
            vr.z = tf32r(v.z); vr.w = tf32r(v.w);
            *(float4*)&Vs[row * 72 + c4 * 4] = vr;
        }
        __syncthreads();

        // ---- S = Q K^T ----
        float c[4][4];
#pragma unroll
        for (int ni = 0; ni < 4; ni++)
#pragma unroll
            for (int e = 0; e < 4; e++) c[ni][e] = 0.f;
#pragma unroll
        for (int kk = 0; kk < 8; kk++) {
            int kb = kk * 8;
            float a[4];
            a[0] = Qs[(kb + tig)     * 72 + r0];
            a[1] = Qs[(kb + tig)     * 72 + r1];
            a[2] = Qs[(kb + tig + 4) * 72 + r0];
            a[3] = Qs[(kb + tig + 4) * 72 + r1];
#pragma unroll
            for (int ni = 0; ni < 4; ni++) {
                int nb = wn * 32 + ni * 8;
                float b[2];
                b[0] = Ks[(kb + tig)     * 72 + nb + g];
                b[1] = Ks[(kb + tig + 4) * 72 + nb + g];
                mma_tf32(c[ni], a, b);
            }
        }

        // ---- rel_pos + scale + causal mask ----
#pragma unroll
        for (int ni = 0; ni < 4; ni++) {
            int kc = wn * 32 + ni * 8 + tig * 2;
            int kj = j0 + kc;
            float2 rp0 = *(const float2*)(relrow0 + j0 + kc);
            float2 rp1 = *(const float2*)(relrow1 + j0 + kc);
            c[ni][0] = (kj     <= qi0 + XLx) ? (c[ni][0] + rp0.x) * 0.125f : -1e30f;
            c[ni][1] = (kj + 1 <= qi0 + XLx) ? (c[ni][1] + rp0.y) * 0.125f : -1e30f;
            c[ni][2] = (kj     <= qi1 + XLx) ? (c[ni][2] + rp1.x) * 0.125f : -1e30f;
            c[ni][3] = (kj + 1 <= qi1 + XLx) ? (c[ni][3] + rp1.y) * 0.125f : -1e30f;
        }

        // ---- online softmax (cross-warp via smem halves) ----
        float rm0 = -1e30f, rm1 = -1e30f;
#pragma unroll
        for (int ni = 0; ni < 4; ni++) {
            rm0 = fmaxf(rm0, fmaxf(c[ni][0], c[ni][1]));
            rm1 = fmaxf(rm1, fmaxf(c[ni][2], c[ni][3]));
        }
        rm0 = fmaxf(rm0, __shfl_xor_sync(0xffffffffu, rm0, 1));
        rm0 = fmaxf(rm0, __shfl_xor_sync(0xffffffffu, rm0, 2));
        rm1 = fmaxf(rm1, __shfl_xor_sync(0xffffffffu, rm1, 1));
        rm1 = fmaxf(rm1, __shfl_xor_sync(0xffffffffu, rm1, 2));
        if (tig == 0) {
            Mh[wn * 64 + r0] = rm0;
            Mh[wn * 64 + r1] = rm1;
        }
        __syncthreads();

        float mn0 = fmaxf(mrow0, fmaxf(Mh[r0], Mh[64 + r0]));
        float mn1 = fmaxf(mrow1, fmaxf(Mh[r1], Mh[64 + r1]));
        float al0 = __expf(mrow0 - mn0);
        float al1 = __expf(mrow1 - mn1);
        float ls0 = 0.f, ls1 = 0.f;
#pragma unroll
        for (int ni = 0; ni < 4; ni++) {
            int kc = wn * 32 + ni * 8 + tig * 2;
            float p00 = tf32r(__expf(c[ni][0] - mn0));
            float p01 = tf32r(__expf(c[ni][1] - mn0));
            float p10 = tf32r(__expf(c[ni][2] - mn1));
            float p11 = tf32r(__expf(c[ni][3] - mn1));
            ls0 += p00 + p01;
            ls1 += p10 + p11;
            Ps[(kc)     * 72 + r0] = p00;
            Ps[(kc + 1) * 72 + r0] = p01;
            Ps[(kc)     * 72 + r1] = p10;
            Ps[(kc + 1) * 72 + r1] = p11;
        }
        ls0 += __shfl_xor_sync(0xffffffffu, ls0, 1);
        ls0 += __shfl_xor_sync(0xffffffffu, ls0, 2);
        ls1 += __shfl_xor_sync(0xffffffffu, ls1, 1);
        ls1 += __shfl_xor_sync(0xffffffffu, ls1, 2);
        if (tig == 0) {
            Lh[wn * 64 + r0] = ls0;
            Lh[wn * 64 + r1] = ls1;
        }
        __syncthreads();

        lrow0 = lrow0 * al0 + Lh[r0] + Lh[64 + r0];
        lrow1 = lrow1 * al1 + Lh[r1] + Lh[64 + r1];
        mrow0 = mn0; mrow1 = mn1;
#pragma unroll
        for (int ni = 0; ni < 4; ni++) {
            o[ni][0] *= al0; o[ni][1] *= al0;
            o[ni][2] *= al1; o[ni][3] *= al1;
        }

        // ---- O += P V ----
#pragma unroll
        for (int kk = 0; kk < 8; kk++) {
            int kb = kk * 8;
            float a[4];
            a[0] = Ps[(kb + tig)     * 72 + r0];
            a[1] = Ps[(kb + tig)     * 72 + r1];
            a[2] = Ps[(kb + tig + 4) * 72 + r0];
            a[3] = Ps[(kb + tig + 4) * 72 + r1];
#pragma unroll
            for (int ni = 0; ni < 4; ni++) {
                int nb = wn * 32 + ni * 8;
                float b[2];
                b[0] = Vs[(kb + tig)     * 72 + nb + g];
                b[1] = Vs[(kb + tig + 4) * 72 + nb + g];
                mma_tf32(o[ni], a, b);
            }
        }
    }

    float gsig = 1.f / (1.f + __expf(-gate[h]));
    float inv0 = gsig / lrow0, inv1 = gsig / lrow1;
#pragma unroll
    for (int ni = 0; ni < 4; ni++) {
        int d = wn * 32 + ni * 8 + tig * 2;
        float2 s0, s1;
        s0.x = o[ni][0] * inv0; s0.y = o[ni][1] * inv0;
        s1.x = o[ni][2] * inv1; s1.y = o[ni][3] * inv1;
        *(float2*)&g_loc[(((size_t)bh) * Sx + qi0) * Dx + d] = s0;
        *(float2*)&g_loc[(((size_t)bh) * Sx + qi1) * Dx + d] = s1;
    }
}

// ---------------------------------------------------------------------------
// kNN external-memory attention + gated merge (unchanged from round 1).
// ---------------------------------------------------------------------------
__global__ __launch_bounds__(64) void knn_kernel(const float* __restrict__ knn,
                                                 const float* __restrict__ gate)
{
    __shared__ float qsh[2][64];
    __shared__ float vsh[2][32][68];

    int s = blockIdx.x, b = blockIdx.y, hp = blockIdx.z;
    int wid = threadIdx.x >> 5, lane = threadIdx.x & 31;
    int h = hp * 2 + wid;

    const float* qp = g_q + (((size_t)(b * Hx + h)) * Sx + s) * Dx;
    qsh[wid][lane]      = qp[lane];
    qsh[wid][lane + 32] = qp[lane + 32];
    __syncwarp();

    const float* kp = knn + ((((size_t)(b * Sx + s)) * KKx + lane) * 2 + 0) * HDx
                          + h * 64;
    float sc = 0.f;
#pragma unroll
    for (int i = 0; i < 16; i++) {
        float4 kf = *(const float4*)(kp + i * 4);
        float4 qf = *(const float4*)&qsh[wid][i * 4];
        sc = fmaf(qf.x, kf.x, sc);
        sc = fmaf(qf.y, kf.y, sc);
        sc = fmaf(qf.z, kf.z, sc);
        sc = fmaf(qf.w, kf.w, sc);
    }
    sc *= 0.125f;

    float mx = sc;
    mx = fmaxf(mx, __shfl_xor_sync(0xffffffffu, mx, 16));
    mx = fmaxf(mx, __shfl_xor_sync(0xffffffffu, mx, 8));
    mx = fmaxf(mx, __shfl_xor_sync(0xffffffffu, mx, 4));
    mx = fmaxf(mx, __shfl_xor_sync(0xffffffffu, mx, 2));
    mx = fmaxf(mx, __shfl_xor_sync(0xffffffffu, mx, 1));
    float p = __expf(sc - mx);
    float sum = p;
    sum += __shfl_xor_sync(0xffffffffu, sum, 16);
    sum += __shfl_xor_sync(0xffffffffu, sum, 8);
    sum += __shfl_xor_sync(0xffffffffu, sum, 4);
    sum += __shfl_xor_sync(0xffffffffu, sum, 2);
    sum += __shfl_xor_sync(0xffffffffu, sum, 1);
    p /= sum;

    const float* vp = kp + HDx;  // slot 1 (values)
#pragma unroll
    for (int i = 0; i < 16; i++) {
        float4 vf = *(const float4*)(vp + i * 4);
        vsh[wid][lane][i * 4 + 0] = p * vf.x;
        vsh[wid][lane][i * 4 + 1] = p * vf.y;
        vsh[wid][lane][i * 4 + 2] = p * vf.z;
        vsh[wid][lane][i * 4 + 3] = p * vf.w;
    }
    __syncwarp();

    float acc0 = 0.f, acc1 = 0.f;
#pragma unroll
    for (int kk = 0; kk < 32; kk++) {
        acc0 += vsh[wid][kk][lane];
        acc1 += vsh[wid][kk][lane + 32];
    }

    float g = 1.f / (1.f + __expf(-gate[h]));
    float w = 1.f - g;
    size_t li = (((size_t)(b * Hx + h)) * Sx + s) * Dx;
    size_t mi = ((size_t)(b * Sx + s)) * HDx + h * 64;
    g_merged[mi + lane]      = g_loc[li + lane]      + w * acc0;
    g_merged[mi + lane + 32] = g_loc[li + lane + 32] + w * acc1;
}

// ---------------------------------------------------------------------------
extern "C" void kernel_launch(void* const* d_in, const int* in_sizes, int n_in,
                              void* d_out, int out_size)
{
    (void)in_sizes; (void)n_in; (void)out_size;
    const float* x    = (const float*)d_in[0];
    const float* rel  = (const float*)d_in[1];
    const float* xlm  = (const float*)d_in[2];
    const float* knn  = (const float*)d_in[3];
    const float* Wq   = (const float*)d_in[4];
    const float* bq   = (const float*)d_in[5];
    const float* Wk   = (const float*)d_in[6];
    const float* bk   = (const float*)d_in[7];
    const float* Wv   = (const float*)d_in[8];
    const float* bv   = (const float*)d_in[9];
    const float* Wo   = (const float*)d_in[10];
    const float* bo   = (const float*)d_in[11];
    const float* gate = (const float*)d_in[12];

    float* out   = (float*)d_out;                       // [4,1024,512]
    float* kvout = out + (size_t)Bx * Sx * EMBx;        // [4,1024,2,512]

    const int smem1 = (128 * 36 + 64 * 36) * (int)sizeof(float);       // 27,648
    const int smem3 = 2 * (128 * 36 + 64 * 36) * (int)sizeof(float);   // 55,296
    cudaFuncSetAttribute(gemm_mma<3>,
                         cudaFuncAttributeMaxDynamicSharedMemorySize, smem3);

    xl_copy<<<4096, 256>>>(xlm);

    dim3 gg(32, 8);
    gemm_mma<1><<<gg, 256, smem1>>>(x, Wq, bq, nullptr, 0);
    gemm_mma<3><<<gg, 256, smem3>>>(x, Wk, bk, kvout, 1);
    gemm_mma<3><<<gg, 256, smem3>>>(x, Wv, bv, kvout, 2);

    const int asmem = (4 * 64 * 72 + 256) * (int)sizeof(float);        // 74,752
    cudaFuncSetAttribute(local_attn_mma,
                         cudaFuncAttributeMaxDynamicSharedMemorySize, asmem);
    local_attn_mma<<<dim3(32, 16), 256, asmem>>>(rel, gate);

    knn_kernel<<<dim3(Sx, Bx, Hx / 2), 64>>>(knn, gate);

    gemm_mma<3><<<gg, 256, smem3>>>(nullptr, Wo, bo, out, 3);
}

// round 3
// speedup vs baseline: 1.7134x; 1.1302x over previous
#include <cuda_runtime.h>
#include <cstdint>

#define Bx   4
#define Sx   1024
#define Hx   8
#define Dx   64
#define HDx  512
#define EMBx 512
#define XLx  1024
#define Jx   2048
#define KKx  32

// ---------------- device scratch ----------------
__device__ float g_q[Bx * Hx * Sx * Dx];
__device__ float g_k[Bx * Hx * Jx * Dx];
__device__ float g_v[Bx * Hx * Jx * Dx];
__device__ float g_loc[Bx * Hx * Sx * Dx];   // g * local attn out  [b,h,s,d]
__device__ float g_ext[Bx * Sx * HDx];       // (1-g) * knn out     [b*s, h*d]

// ---------------- tf32 helpers ----------------
__device__ __forceinline__ float tf32r(float x) {
    uint32_t u;
    asm("cvt.rna.tf32.f32 %0, %1;" : "=r"(u) : "f"(x));
    return __uint_as_float(u);
}
__device__ __forceinline__ float4 tf32r4(float4 f) {
    f.x = tf32r(f.x); f.y = tf32r(f.y); f.z = tf32r(f.z); f.w = tf32r(f.w);
    return f;
}
__device__ __forceinline__ void mma_tf32(float* c, const float* a, const float* b)
{
    asm volatile(
        "mma.sync.aligned.m16n8k8.row.col.f32.tf32.tf32.f32 "
        "{%0,%1,%2,%3},{%4,%5,%6,%7},{%8,%9},{%0,%1,%2,%3};\n"
        : "+f"(c[0]), "+f"(c[1]), "+f"(c[2]), "+f"(c[3])
        : "r"(__float_as_uint(a[0])), "r"(__float_as_uint(a[1])),
          "r"(__float_as_uint(a[2])), "r"(__float_as_uint(a[3])),
          "r"(__float_as_uint(b[0])), "r"(__float_as_uint(b[1])));
}

// ===========================================================================
// Fused QKV projection GEMM (+ xl_memory copy blocks).
// Blocks [0,768): GEMM C[4096, 1536] in 128x64 tiles:
//   m-block = blockIdx.x & 31, n-block = blockIdx.x >> 5 (0..23)
//   nsec = n-block / 8 -> 0:Q (1xTF32), 1:K, 2:V (3xTF32)
// Blocks [768, 1792): copy xl_memory -> g_k / g_v rows 0..XL-1
// ===========================================================================
__global__ __launch_bounds__(256) void qkv_gemm(
    const float* __restrict__ x,
    const float* __restrict__ Wq, const float* __restrict__ bq,
    const float* __restrict__ Wk, const float* __restrict__ bk,
    const float* __restrict__ Wv, const float* __restrict__ bv,
    const float* __restrict__ xlm,
    float* __restrict__ kvout)
{
    extern __shared__ float smg[];

    if (blockIdx.x >= 768) {
        // ---- xl copy ----
        int base = (blockIdx.x - 768) * 1024;
#pragma unroll
        for (int i = 0; i < 4; i++) {
            int idx = base + i * 256 + threadIdx.x;       // float4 index
            int n4 = idx & 127;
            int rest = idx >> 7;
            int c = rest & 1;  rest >>= 1;
            int j = rest & 1023;
            int b = rest >> 10;
            float4 f = ((const float4*)xlm)[idx];
            int n = n4 * 4;
            int h = n >> 6, d = n & 63;
            float* dst = (c ? g_v : g_k) + (((size_t)(b * Hx + h)) * Jx + j) * Dx + d;
            *(float4*)dst = f;
        }
        return;
    }

    float* Ab = smg;                     // [128][36]
    float* Bb = Ab + 128 * 36;           // [64][36]
    float* Al = Bb + 64 * 36;
    float* Bl = Al + 128 * 36;

    int bm   = blockIdx.x & 31;
    int nbi  = blockIdx.x >> 5;          // 0..23
    int nsec = nbi >> 3;                 // 0,1,2
    int m0 = bm * 128, n0 = (nbi & 7) * 64;
    bool s3 = (nsec != 0);

    const float* W    = (nsec == 0) ? Wq : (nsec == 1) ? Wk : Wv;
    const float* bias = (nsec == 0) ? bq : (nsec == 1) ? bk : bv;

    int tid = threadIdx.x;
    int wid = tid >> 5, lane = tid & 31;
    int wm = wid & 3, wn = wid >> 2;
    int g = lane >> 2, tig = lane & 3;

    float acc[2][4][4];
#pragma unroll
    for (int i = 0; i < 2; i++)
#pragma unroll
        for (int j = 0; j < 4; j++)
#pragma unroll
            for (int e = 0; e < 4; e++) acc[i][j][e] = 0.f;

    int a_row = tid >> 1;
    int a_c0  = (tid & 1) * 16;
    int b_row = tid >> 2;
    int b_c0  = (tid & 3) * 8;

    const float* Agp = x + (size_t)(m0 + a_row) * 512 + a_c0;
    const float* Wgp = W + (size_t)(n0 + b_row) * 512 + b_c0;

    for (int kc = 0; kc < 16; kc++) {
        int k0 = kc * 32;
        __syncthreads();
#pragma unroll
        for (int i = 0; i < 4; i++) {
            float4 f = *(const float4*)(Agp + k0 + i * 4);
            float4 bg = tf32r4(f);
            *(float4*)&Ab[a_row * 36 + a_c0 + i * 4] = bg;
            if (s3) {
                float4 sl;
                sl.x = tf32r(f.x - bg.x); sl.y = tf32r(f.y - bg.y);
                sl.z = tf32r(f.z - bg.z); sl.w = tf32r(f.w - bg.w);
                *(float4*)&Al[a_row * 36 + a_c0 + i * 4] = sl;
            }
        }
#pragma unroll
        for (int i = 0; i < 2; i++) {
            float4 f = *(const float4*)(Wgp + k0 + i * 4);
            float4 bg = tf32r4(f);
            *(float4*)&Bb[b_row * 36 + b_c0 + i * 4] = bg;
            if (s3) {
                float4 sl;
                sl.x = tf32r(f.x - bg.x); sl.y = tf32r(f.y - bg.y);
                sl.z = tf32r(f.z - bg.z); sl.w = tf32r(f.w - bg.w);
                *(float4*)&Bl[b_row * 36 + b_c0 + i * 4] = sl;
            }
        }
        __syncthreads();

#pragma unroll
        for (int kk = 0; kk < 4; kk++) {
            int kb = kk * 8;
            float a[2][4], as[2][4];
#pragma unroll
            for (int mi = 0; mi < 2; mi++) {
                int base = wm * 32 + mi * 16;
                a[mi][0] = Ab[(base + g)     * 36 + kb + tig];
                a[mi][1] = Ab[(base + g + 8) * 36 + kb + tig];
                a[mi][2] = Ab[(base + g)     * 36 + kb + tig + 4];
                a[mi][3] = Ab[(base + g + 8) * 36 + kb + tig + 4];
                if (s3) {
                    as[mi][0] = Al[(base + g)     * 36 + kb + tig];
                    as[mi][1] = Al[(base + g + 8) * 36 + kb + tig];
                    as[mi][2] = Al[(base + g)     * 36 + kb + tig + 4];
                    as[mi][3] = Al[(base + g + 8) * 36 + kb + tig + 4];
                }
            }
            float b[4][2], bs[4][2];
#pragma unroll
            for (int ni = 0; ni < 4; ni++) {
                int nb = wn * 32 + ni * 8;
                b[ni][0] = Bb[(nb + g) * 36 + kb + tig];
                b[ni][1] = Bb[(nb + g) * 36 + kb + tig + 4];
                if (s3) {
                    bs[ni][0] = Bl[(nb + g) * 36 + kb + tig];
                    bs[ni][1] = Bl[(nb + g) * 36 + kb + tig + 4];
                }
            }
#pragma unroll
            for (int mi = 0; mi < 2; mi++)
#pragma unroll
                for (int ni = 0; ni < 4; ni++) {
                    mma_tf32(acc[mi][ni], a[mi], b[ni]);
                    if (s3) {
                        mma_tf32(acc[mi][ni], a[mi], bs[ni]);
                        mma_tf32(acc[mi][ni], as[mi], b[ni]);
                    }
                }
        }
    }

#pragma unroll
    for (int mi = 0; mi < 2; mi++) {
#pragma unroll
        for (int ni = 0; ni < 4; ni++) {
#pragma unroll
            for (int e = 0; e < 4; e++) {
                int m = m0 + wm * 32 + mi * 16 + g + ((e >> 1) * 8);
                int n = n0 + wn * 32 + ni * 8 + tig * 2 + (e & 1);
                float c = acc[mi][ni][e] + bias[n];
                int b = m >> 10, s = m & 1023;
                int h = n >> 6, d = n & 63;
                if (nsec == 0) {
                    g_q[(((size_t)(b * Hx + h)) * Sx + s) * Dx + d] = c;
                } else if (nsec == 1) {
                    g_k[(((size_t)(b * Hx + h)) * Jx + XLx + s) * Dx + d] = c;
                    kvout[(((size_t)(b * Sx + s)) * 2 + 0) * HDx + n] = c;
                } else {
                    g_v[(((size_t)(b * Hx + h)) * Jx + XLx + s) * Dx + d] = c;
                    kvout[(((size_t)(b * Sx + s)) * 2 + 1) * HDx + n] = c;
                }
            }
        }
    }
}

// ===========================================================================
// Fused attention + kNN kernel.
// Blocks [0,512): local causal XL flash attention, split-key softmax.
//   bh = blockIdx.x >> 4, qt = blockIdx.x & 15
//   8 warps: wm = wid&3 (16-query strip), wn = wid>>2 (32-key half)
// Blocks [512, 4608): kNN attention, one warp per (b,s,h), writes g_ext.
// ===========================================================================
__global__ __launch_bounds__(256) void attn_knn(const float* __restrict__ rel,
                                                const float* __restrict__ gate,
                                                const float* __restrict__ knn)
{
    extern __shared__ float sm[];
    int tid = threadIdx.x;
    int wid = tid >> 5, lane = tid & 31;

    if (blockIdx.x >= 512) {
        // ------------------- kNN part -------------------
        int kb2 = blockIdx.x - 512;          // 0..4095
        int b = kb2 >> 10, s = kb2 & 1023;
        int h = wid;
        float* qsh = sm + wid * 2176;        // [64]
        float* vsh = qsh + 64;               // [32][66]

        const float* qp = g_q + (((size_t)(b * Hx + h)) * Sx + s) * Dx;
        qsh[lane]      = qp[lane];
        qsh[lane + 32] = qp[lane + 32];
        __syncwarp();

        const float* kp = knn + ((((size_t)(b * Sx + s)) * KKx + lane) * 2) * HDx
                              + h * 64;
        float sc = 0.f;
#pragma unroll
        for (int i = 0; i < 16; i++) {
            float4 kf = *(const float4*)(kp + i * 4);
            float4 qf = *(const float4*)&qsh[i * 4];
            sc = fmaf(qf.x, kf.x, sc);
            sc = fmaf(qf.y, kf.y, sc);
            sc = fmaf(qf.z, kf.z, sc);
            sc = fmaf(qf.w, kf.w, sc);
        }
        sc *= 0.125f;

        float mx = sc;
        mx = fmaxf(mx, __shfl_xor_sync(0xffffffffu, mx, 16));
        mx = fmaxf(mx, __shfl_xor_sync(0xffffffffu, mx, 8));
        mx = fmaxf(mx, __shfl_xor_sync(0xffffffffu, mx, 4));
        mx = fmaxf(mx, __shfl_xor_sync(0xffffffffu, mx, 2));
        mx = fmaxf(mx, __shfl_xor_sync(0xffffffffu, mx, 1));
        float p = __expf(sc - mx);
        float sum = p;
        sum += __shfl_xor_sync(0xffffffffu, sum, 16);
        sum += __shfl_xor_sync(0xffffffffu, sum, 8);
        sum += __shfl_xor_sync(0xffffffffu, sum, 4);
        sum += __shfl_xor_sync(0xffffffffu, sum, 2);
        sum += __shfl_xor_sync(0xffffffffu, sum, 1);
        p /= sum;

        const float* vp = kp + HDx;
#pragma unroll
        for (int i = 0; i < 16; i++) {
            float4 vf = *(const float4*)(vp + i * 4);
            vsh[lane * 66 + i * 4 + 0] = p * vf.x;
            vsh[lane * 66 + i * 4 + 1] = p * vf.y;
            vsh[lane * 66 + i * 4 + 2] = p * vf.z;
            vsh[lane * 66 + i * 4 + 3] = p * vf.w;
        }
        __syncwarp();

        float acc0 = 0.f, acc1 = 0.f;
#pragma unroll
        for (int kk = 0; kk < 32; kk++) {
            acc0 += vsh[kk * 66 + lane];
            acc1 += vsh[kk * 66 + lane + 32];
        }

        float gg = 1.f / (1.f + __expf(-gate[h]));
        float w = 1.f - gg;
        size_t mi = ((size_t)(b * Sx + s)) * HDx + h * 64;
        g_ext[mi + lane]      = w * acc0;
        g_ext[mi + lane + 32] = w * acc1;
        return;
    }

    // ------------------- attention part -------------------
    float* Qs = sm;                       // [64][68] row=q
    float* Ks = Qs + 64 * 68;             // [64][68] row=key
    float* Vs = Ks + 64 * 68;             // [64][68] row=key
    float* Pw = Vs + 64 * 68 + wid * 576; // per-warp [16][36]

    int bh = blockIdx.x >> 4;             // b*8 + h
    int h = bh & 7;
    int qt = blockIdx.x & 15;
    int i0 = qt * 64;
    int wm = wid & 3, wn = wid >> 2;
    int g = lane >> 2, tig = lane & 3;
    int r0 = wm * 16 + g, r1 = r0 + 8;
    int qi0 = i0 + r0, qi1 = i0 + r1;

    const float* qbase = g_q + (((size_t)bh) * Sx + i0) * Dx;
    for (int idx = tid; idx < 1024; idx += 256) {
        int row = idx >> 4, c4 = idx & 15;
        *(float4*)&Qs[row * 68 + c4 * 4] =
            tf32r4(*(const float4*)(qbase + row * 64 + c4 * 4));
    }

    float o[8][4];
#pragma unroll
    for (int ni = 0; ni < 8; ni++)
#pragma unroll
        for (int e = 0; e < 4; e++) o[ni][e] = 0.f;
    float m0 = -1e30f, m1 = -1e30f, l0 = 0.f, l1 = 0.f;

    int ntiles = qt + 17;
    const float* kbase = g_k + ((size_t)bh) * Jx * Dx;
    const float* vbase = g_v + ((size_t)bh) * Jx * Dx;
    const float* relrow0 = rel + ((size_t)h * Sx + qi0) * Jx;
    const float* relrow1 = rel + ((size_t)h * Sx + qi1) * Jx;

    for (int t = 0; t < ntiles; t++) {
        int j0 = t * 64;
        __syncthreads();
        for (int idx = tid; idx < 1024; idx += 256) {
            int row = idx >> 4, c4 = idx & 15;
            *(float4*)&Ks[row * 68 + c4 * 4] =
                tf32r4(*(const float4*)(kbase + (size_t)(j0 + row) * 64 + c4 * 4));
            *(float4*)&Vs[row * 68 + c4 * 4] =
                tf32r4(*(const float4*)(vbase + (size_t)(j0 + row) * 64 + c4 * 4));
        }
        __syncthreads();

        // ---- S = Q K^T over this warp's 32-key half ----
        float c[4][4];
#pragma unroll
        for (int ni = 0; ni < 4; ni++)
#pragma unroll
            for (int e = 0; e < 4; e++) c[ni][e] = 0.f;
#pragma unroll
        for (int kk = 0; kk < 8; kk++) {
            int kb = kk * 8;
            float a[4];
            a[0] = Qs[r0 * 68 + kb + tig];
            a[1] = Qs[r1 * 68 + kb + tig];
            a[2] = Qs[r0 * 68 + kb + tig + 4];
            a[3] = Qs[r1 * 68 + kb + tig + 4];
#pragma unroll
            for (int ni = 0; ni < 4; ni++) {
                int krow = wn * 32 + ni * 8 + g;
                float b[2];
                b[0] = Ks[krow * 68 + kb + tig];
                b[1] = Ks[krow * 68 + kb + tig + 4];
                mma_tf32(c[ni], a, b);
            }
        }

        // ---- rel_pos + scale + causal mask ----
#pragma unroll
        for (int ni = 0; ni < 4; ni++) {
            int kcol = wn * 32 + ni * 8 + tig * 2;
            int kj = j0 + kcol;
            float2 rp0 = *(const float2*)(relrow0 + kj);
            float2 rp1 = *(const float2*)(relrow1 + kj);
            c[ni][0] = (kj     <= qi0 + XLx) ? (c[ni][0] + rp0.x) * 0.125f : -1e30f;
            c[ni][1] = (kj + 1 <= qi0 + XLx) ? (c[ni][1] + rp0.y) * 0.125f : -1e30f;
            c[ni][2] = (kj     <= qi1 + XLx) ? (c[ni][2] + rp1.x) * 0.125f : -1e30f;
            c[ni][3] = (kj + 1 <= qi1 + XLx) ? (c[ni][3] + rp1.y) * 0.125f : -1e30f;
        }

        // ---- warp-private online softmax over the 32-key half ----
        float rm0 = -1e30f, rm1 = -1e30f;
#pragma unroll
        for (int ni = 0; ni < 4; ni++) {
            rm0 = fmaxf(rm0, fmaxf(c[ni][0], c[ni][1]));
            rm1 = fmaxf(rm1, fmaxf(c[ni][2], c[ni][3]));
        }
        rm0 = fmaxf(rm0, __shfl_xor_sync(0xffffffffu, rm0, 1));
        rm0 = fmaxf(rm0, __shfl_xor_sync(0xffffffffu, rm0, 2));
        rm1 = fmaxf(rm1, __shfl_xor_sync(0xffffffffu, rm1, 1));
        rm1 = fmaxf(rm1, __shfl_xor_sync(0xffffffffu, rm1, 2));
        float mn0 = fmaxf(m0, rm0), mn1 = fmaxf(m1, rm1);
        float al0 = __expf(m0 - mn0), al1 = __expf(m1 - mn1);
        float ls0 = 0.f, ls1 = 0.f;
#pragma unroll
        for (int ni = 0; ni < 4; ni++) {
            int kcol = ni * 8 + tig * 2;
            float p00 = tf32r(__expf(c[ni][0] - mn0));
            float p01 = tf32r(__expf(c[ni][1] - mn0));
            float p10 = tf32r(__expf(c[ni][2] - mn1));
            float p11 = tf32r(__expf(c[ni][3] - mn1));
            ls0 += p00 + p01; ls1 += p10 + p11;
            Pw[g * 36 + kcol]           = p00;
            Pw[g * 36 + kcol + 1]       = p01;
            Pw[(g + 8) * 36 + kcol]     = p10;
            Pw[(g + 8) * 36 + kcol + 1] = p11;
        }
        ls0 += __shfl_xor_sync(0xffffffffu, ls0, 1);
        ls0 += __shfl_xor_sync(0xffffffffu, ls0, 2);
        ls1 += __shfl_xor_sync(0xffffffffu, ls1, 1);
        ls1 += __shfl_xor_sync(0xffffffffu, ls1, 2);
        l0 = l0 * al0 + ls0;
        l1 = l1 * al1 + ls1;
        m0 = mn0; m1 = mn1;
#pragma unroll
        for (int ni = 0; ni < 8; ni++) {
            o[ni][0] *= al0; o[ni][1] *= al0;
            o[ni][2] *= al1; o[ni][3] *= al1;
        }
        __syncwarp();

        // ---- O += P V  (k = 32 keys of this half, n = all 64 dims) ----
#pragma unroll
        for (int kk = 0; kk < 4; kk++) {
            int kb = kk * 8;
            float a[4];
            a[0] = Pw[g * 36 + kb + tig];
            a[1] = Pw[(g + 8) * 36 + kb + tig];
            a[2] = Pw[g * 36 + kb + tig + 4];
            a[3] = Pw[(g + 8) * 36 + kb + tig + 4];
            int vrow = wn * 32 + kb + tig;
#pragma unroll
            for (int ni = 0; ni < 8; ni++) {
                float b[2];
                b[0] = Vs[vrow * 68 + ni * 8 + g];
                b[1] = Vs[(vrow + 4) * 68 + ni * 8 + g];
                mma_tf32(o[ni], a, b);
            }
        }
    }

    // ---- merge the two key-halves ----
    __syncthreads();
    if (wn == 1) {
        float* M = Ks + (wm * 16) * 68;
#pragma unroll
        for (int ni = 0; ni < 8; ni++) {
            int col = ni * 8 + tig * 2;
            M[g * 68 + col]           = o[ni][0];
            M[g * 68 + col + 1]       = o[ni][1];
            M[(g + 8) * 68 + col]     = o[ni][2];
            M[(g + 8) * 68 + col + 1] = o[ni][3];
        }
        if (tig == 0) {
            Vs[r0] = m0; Vs[r1] = m1;
            Vs[64 + r0] = l0; Vs[64 + r1] = l1;
        }
    }
    __syncthreads();
    if (wn == 0) {
        float gsig = 1.f / (1.f + __expf(-gate[h]));
        float m1p0 = Vs[r0], m1p1 = Vs[r1];
        float l1p0 = Vs[64 + r0], l1p1 = Vs[64 + r1];
        float mt0 = fmaxf(m0, m1p0), mt1 = fmaxf(m1, m1p1);
        float a00 = __expf(m0 - mt0),   a01 = __expf(m1p0 - mt0);
        float a10 = __expf(m1 - mt1),   a11 = __expf(m1p1 - mt1);
        float inv0 = gsig / (l0 * a00 + l1p0 * a01);
        float inv1 = gsig / (l1 * a10 + l1p1 * a11);
        float* M = Ks + (wm * 16) * 68;
#pragma unroll
        for (int ni = 0; ni < 8; ni++) {
            int col = ni * 8 + tig * 2;
            float2 s0, s1;
            s0.x = (o[ni][0] * a00 + M[g * 68 + col]           * a01) * inv0;
            s0.y = (o[ni][1] * a00 + M[g * 68 + col + 1]       * a01) * inv0;
            s1.x = (o[ni][2] * a10 + M[(g + 8) * 68 + col]     * a11) * inv1;
            s1.y = (o[ni][3] * a10 + M[(g + 8) * 68 + col + 1] * a11) * inv1;
            *(float2*)&g_loc[(((size_t)bh) * Sx + qi0) * Dx + col] = s0;
            *(float2*)&g_loc[(((size_t)bh) * Sx + qi1) * Dx + col] = s1;
        }
    }
}

// ===========================================================================
// Output projection GEMM: out[4096,512] = (g_loc + g_ext) @ Wo^T + bo, 3xTF32
// ===========================================================================
__global__ __launch_bounds__(256) void out_gemm(const float* __restrict__ W,
                                                const float* __restrict__ bias,
                                                float* __restrict__ dst)
{
    extern __shared__ float smg[];
    float* Ab = smg;
    float* Bb = Ab + 128 * 36;
    float* Al = Bb + 64 * 36;
    float* Bl = Al + 128 * 36;

    int tid = threadIdx.x;
    int wid = tid >> 5, lane = tid & 31;
    int wm = wid & 3, wn = wid >> 2;
    int g = lane >> 2, tig = lane & 3;
    int m0 = blockIdx.x * 128, n0 = blockIdx.y * 64;

    float acc[2][4][4];
#pragma unroll
    for (int i = 0; i < 2; i++)
#pragma unroll
        for (int j = 0; j < 4; j++)
#pragma unroll
            for (int e = 0; e < 4; e++) acc[i][j][e] = 0.f;

    int a_row = tid >> 1;
    int a_c0  = (tid & 1) * 16;
    int b_row = tid >> 2;
    int b_c0  = (tid & 3) * 8;

    int mrow = m0 + a_row;
    int ab = mrow >> 10, as_ = mrow & 1023;
    const float* extp = g_ext + (size_t)mrow * 512;
    const float* Wgp = W + (size_t)(n0 + b_row) * 512 + b_c0;

    for (int kc = 0; kc < 16; kc++) {
        int k0 = kc * 32;
        __syncthreads();
#pragma unroll
        for (int i = 0; i < 4; i++) {
            int cc = a_c0 + k0 + i * 4;
            int hh = cc >> 6, dd = cc & 63;
            float4 f1 = *(const float4*)&g_loc[(((size_t)(ab * Hx + hh)) * Sx + as_) * Dx + dd];
            float4 f2 = *(const float4*)(extp + cc);
            float4 f;
            f.x = f1.x + f2.x; f.y = f1.y + f2.y;
            f.z = f1.z + f2.z; f.w = f1.w + f2.w;
            float4 bg = tf32r4(f);
            *(float4*)&Ab[a_row * 36 + a_c0 + i * 4] = bg;
            float4 sl;
            sl.x = tf32r(f.x - bg.x); sl.y = tf32r(f.y - bg.y);
            sl.z = tf32r(f.z - bg.z); sl.w = tf32r(f.w - bg.w);
            *(float4*)&Al[a_row * 36 + a_c0 + i * 4] = sl;
        }
#pragma unroll
        for (int i = 0; i < 2; i++) {
            float4 f = *(const float4*)(Wgp + k0 + i * 4);
            float4 bg = tf32r4(f);
            *(float4*)&Bb[b_row * 36 + b_c0 + i * 4] = bg;
            float4 sl;
            sl.x = tf32r(f.x - bg.x); sl.y = tf32r(f.y - bg.y);
            sl.z = tf32r(f.z - bg.z); sl.w = tf32r(f.w - bg.w);
            *(float4*)&Bl[b_row * 36 + b_c0 + i * 4] = sl;
        }
        __syncthreads();

#pragma unroll
        for (int kk = 0; kk < 4; kk++) {
            int kb = kk * 8;
            float a[2][4], asr[2][4];
#pragma unroll
            for (int mi = 0; mi < 2; mi++) {
                int base = wm * 32 + mi * 16;
                a[mi][0] = Ab[(base + g)     * 36 + kb + tig];
                a[mi][1] = Ab[(base + g + 8) * 36 + kb + tig];
                a[mi][2] = Ab[(base + g)     * 36 + kb + tig + 4];
                a[mi][3] = Ab[(base + g + 8) * 36 + kb + tig + 4];
                asr[mi][0] = Al[(base + g)     * 36 + kb + tig];
                asr[mi][1] = Al[(base + g + 8) * 36 + kb + tig];
                asr[mi][2] = Al[(base + g)     * 36 + kb + tig + 4];
                asr[mi][3] = Al[(base + g + 8) * 36 + kb + tig + 4];
            }
            float b[4][2], bs[4][2];
#pragma unroll
            for (int ni = 0; ni < 4; ni++) {
                int nb = wn * 32 + ni * 8;
                b[ni][0] = Bb[(nb + g) * 36 + kb + tig];
                b[ni][1] = Bb[(nb + g) * 36 + kb + tig + 4];
                bs[ni][0] = Bl[(nb + g) * 36 + kb + tig];
                bs[ni][1] = Bl[(nb + g) * 36 + kb + tig + 4];
            }
#pragma unroll
            for (int mi = 0; mi < 2; mi++)
#pragma unroll
                for (int ni = 0; ni < 4; ni++) {
                    mma_tf32(acc[mi][ni], a[mi], b[ni]);
                    mma_tf32(acc[mi][ni], a[mi], bs[ni]);
                    mma_tf32(acc[mi][ni], asr[mi], b[ni]);
                }
        }
    }

#pragma unroll
    for (int mi = 0; mi < 2; mi++)
#pragma unroll
        for (int ni = 0; ni < 4; ni++)
#pragma unroll
            for (int e = 0; e < 4; e++) {
                int m = m0 + wm * 32 + mi * 16 + g + ((e >> 1) * 8);
                int n = n0 + wn * 32 + ni * 8 + tig * 2 + (e & 1);
                dst[(size_t)m * EMBx + n] = acc[mi][ni][e] + bias[n];
            }
}

// ---------------------------------------------------------------------------
extern "C" void kernel_launch(void* const* d_in, const int* in_sizes, int n_in,
                              void* d_out, int out_size)
{
    (void)in_sizes; (void)n_in; (void)out_size;
    const float* x    = (const float*)d_in[0];
    const float* rel  = (const float*)d_in[1];
    const float* xlm  = (const float*)d_in[2];
    const float* knn  = (const float*)d_in[3];
    const float* Wq   = (const float*)d_in[4];
    const float* bq   = (const float*)d_in[5];
    const float* Wk   = (const float*)d_in[6];
    const float* bk   = (const float*)d_in[7];
    const float* Wv   = (const float*)d_in[8];
    const float* bv   = (const float*)d_in[9];
    const float* Wo   = (const float*)d_in[10];
    const float* bo   = (const float*)d_in[11];
    const float* gate = (const float*)d_in[12];

    float* out   = (float*)d_out;
    float* kvout = out + (size_t)Bx * Sx * EMBx;

    const int gsm = 2 * (128 * 36 + 64 * 36) * (int)sizeof(float);   // 55,296
    cudaFuncSetAttribute(qkv_gemm,
                         cudaFuncAttributeMaxDynamicSharedMemorySize, gsm);
    qkv_gemm<<<768 + 1024, 256, gsm>>>(x, Wq, bq, Wk, bk, Wv, bv, xlm, kvout);

    const int asmem = (3 * 64 * 68 + 8 * 576) * (int)sizeof(float);  // 70,656
    cudaFuncSetAttribute(attn_knn,
                         cudaFuncAttributeMaxDynamicSharedMemorySize, asmem);
    attn_knn<<<512 + 4096, 256, asmem>>>(rel, gate, knn);

    cudaFuncSetAttribute(out_gemm,
                         cudaFuncAttributeMaxDynamicSharedMemorySize, gsm);
    out_gemm<<<dim3(32, 8), 256, gsm>>>(Wo, bo, out);
}